// round 1
// baseline (speedup 1.0000x reference)
#include <cuda_runtime.h>
#include <math.h>

#define BDIM  2
#define TSEQ  2048
#define CDIM  2048
#define NHEAD 16
#define HD    128

// Scratch (static device globals — no runtime allocation)
__device__ float g_qkv[(size_t)BDIM * TSEQ * 3 * CDIM];   // [B,T,3C]
__device__ float g_att[(size_t)BDIM * TSEQ * CDIM];       // [B,T,C]

// ---------------------------------------------------------------------------
// SGEMM + bias: C[M,N] = A[M,K] @ B[K,N] + bias[N]
// 128x128 block tile, BK=16, 256 threads, 8x8 per thread, float4 everywhere.
// ---------------------------------------------------------------------------
__global__ void __launch_bounds__(256) sgemm_bias_kernel(
    const float* __restrict__ A, const float* __restrict__ B,
    const float* __restrict__ bias, float* __restrict__ C,
    int M, int N, int K)
{
    __shared__ float As[16][128];   // transposed: As[k][m]
    __shared__ float Bs[16][128];   // natural:    Bs[k][n]

    const int tid = threadIdx.x;
    const int tx = tid & 15, ty = tid >> 4;
    const int m0 = blockIdx.y * 128;
    const int n0 = blockIdx.x * 128;

    float acc[8][8];
    #pragma unroll
    for (int i = 0; i < 8; i++)
        #pragma unroll
        for (int j = 0; j < 8; j++) acc[i][j] = 0.f;

    for (int k0 = 0; k0 < K; k0 += 16) {
        // Load A tile 128x16 (float4 along K, store transposed)
        #pragma unroll
        for (int l = 0; l < 2; l++) {
            int lin = tid + l * 256;           // 0..511 float4s
            int r   = lin >> 2;                // row 0..127
            int k4  = (lin & 3) * 4;           // k offset 0,4,8,12
            float4 a = *(const float4*)(A + (size_t)(m0 + r) * K + k0 + k4);
            As[k4 + 0][r] = a.x;
            As[k4 + 1][r] = a.y;
            As[k4 + 2][r] = a.z;
            As[k4 + 3][r] = a.w;
        }
        // Load B tile 16x128 (float4 along N)
        #pragma unroll
        for (int l = 0; l < 2; l++) {
            int lin = tid + l * 256;
            int r   = lin >> 5;                // k row 0..15
            int c4  = (lin & 31) * 4;          // n offset
            *(float4*)&Bs[r][c4] = *(const float4*)(B + (size_t)(k0 + r) * N + n0 + c4);
        }
        __syncthreads();

        #pragma unroll
        for (int kk = 0; kk < 16; kk++) {
            float ra[8], rb[8];
            *(float4*)&ra[0] = *(float4*)&As[kk][ty * 8];
            *(float4*)&ra[4] = *(float4*)&As[kk][ty * 8 + 4];
            *(float4*)&rb[0] = *(float4*)&Bs[kk][tx * 8];
            *(float4*)&rb[4] = *(float4*)&Bs[kk][tx * 8 + 4];
            #pragma unroll
            for (int i = 0; i < 8; i++)
                #pragma unroll
                for (int j = 0; j < 8; j++)
                    acc[i][j] = fmaf(ra[i], rb[j], acc[i][j]);
        }
        __syncthreads();
    }

    // Epilogue: add bias, float4 stores
    float bl[8];
    *(float4*)&bl[0] = *(const float4*)(bias + n0 + tx * 8);
    *(float4*)&bl[4] = *(const float4*)(bias + n0 + tx * 8 + 4);
    #pragma unroll
    for (int i = 0; i < 8; i++) {
        float* cp = C + (size_t)(m0 + ty * 8 + i) * N + n0 + tx * 8;
        float o[8];
        #pragma unroll
        for (int j = 0; j < 8; j++) o[j] = acc[i][j] + bl[j];
        *(float4*)cp       = *(float4*)&o[0];
        *(float4*)(cp + 4) = *(float4*)&o[4];
    }
}

// ---------------------------------------------------------------------------
// FP32 flash attention (causal). 64 queries x 64 keys per tile, hd=128.
// Q,K stored transposed in smem ([d][row]) for conflict-free float4 reads.
// Online softmax; per-thread 4 rows x (4 S cols / 8 O cols).
// grid = (T/64, NHEAD, B), block = 256.
// ---------------------------------------------------------------------------
#define FBM 64
#define FBN 64
#define BMP 68   // padded row stride for transposed tiles (mult of 4)

#define FLASH_SMEM ((HD*BMP + HD*BMP + FBN*HD + FBM*65) * 4)

__global__ void __launch_bounds__(256) flash_kernel(
    const float* __restrict__ qkv, float* __restrict__ out)
{
    extern __shared__ float sm[];
    float* Qt = sm;                 // [HD][BMP]
    float* Kt = Qt + HD * BMP;      // [HD][BMP]
    float* Vs = Kt + HD * BMP;      // [FBN][HD]
    float* Ps = Vs + FBN * HD;      // [FBM][65]

    const int qi  = blockIdx.x;
    const int h   = blockIdx.y;
    const int b   = blockIdx.z;
    const int tid = threadIdx.x;
    const int tx  = tid & 15, ty = tid >> 4;
    const int q0  = qi * FBM;
    const float scale_q = 0.08838834764831844f;  // 1/sqrt(128)

    const float* qb = qkv + (size_t)b * TSEQ * 3 * CDIM + h * HD;
    const float* kb = qb + CDIM;
    const float* vb = qb + 2 * CDIM;

    // Load Q tile transposed, pre-scaled
    #pragma unroll
    for (int l = 0; l < 8; l++) {
        int lin = tid + l * 256;        // 0..2047 float4s
        int r   = lin >> 5;             // row (HD/4=32 float4 per row)
        int d4  = (lin & 31) * 4;
        float4 v = *(const float4*)(qb + (size_t)(q0 + r) * 3 * CDIM + d4);
        Qt[(d4 + 0) * BMP + r] = v.x * scale_q;
        Qt[(d4 + 1) * BMP + r] = v.y * scale_q;
        Qt[(d4 + 2) * BMP + r] = v.z * scale_q;
        Qt[(d4 + 3) * BMP + r] = v.w * scale_q;
    }

    float m_i[4], l_i[4], O[4][8];
    #pragma unroll
    for (int i = 0; i < 4; i++) {
        m_i[i] = -INFINITY; l_i[i] = 0.f;
        #pragma unroll
        for (int j = 0; j < 8; j++) O[i][j] = 0.f;
    }

    for (int j = 0; j <= qi; j++) {
        __syncthreads();   // prev PV / Q-load complete before overwriting K,V
        // Load K tile transposed + V tile natural
        #pragma unroll
        for (int l = 0; l < 8; l++) {
            int lin = tid + l * 256;
            int r   = lin >> 5;
            int d4  = (lin & 31) * 4;
            size_t goff = (size_t)(j * FBN + r) * 3 * CDIM + d4;
            float4 kv = *(const float4*)(kb + goff);
            Kt[(d4 + 0) * BMP + r] = kv.x;
            Kt[(d4 + 1) * BMP + r] = kv.y;
            Kt[(d4 + 2) * BMP + r] = kv.z;
            Kt[(d4 + 3) * BMP + r] = kv.w;
            *(float4*)&Vs[r * HD + d4] = *(const float4*)(vb + goff);
        }
        __syncthreads();

        // S = Q K^T (4x4 per thread)
        float acc[4][4];
        #pragma unroll
        for (int i = 0; i < 4; i++)
            #pragma unroll
            for (int jj = 0; jj < 4; jj++) acc[i][jj] = 0.f;

        #pragma unroll 8
        for (int d = 0; d < HD; d++) {
            float qr[4], kr[4];
            *(float4*)qr = *(float4*)&Qt[d * BMP + ty * 4];
            *(float4*)kr = *(float4*)&Kt[d * BMP + tx * 4];
            #pragma unroll
            for (int i = 0; i < 4; i++)
                #pragma unroll
                for (int jj = 0; jj < 4; jj++)
                    acc[i][jj] = fmaf(qr[i], kr[jj], acc[i][jj]);
        }

        // Causal mask on diagonal tile
        if (j == qi) {
            #pragma unroll
            for (int i = 0; i < 4; i++)
                #pragma unroll
                for (int jj = 0; jj < 4; jj++)
                    if (tx * 4 + jj > ty * 4 + i) acc[i][jj] = -INFINITY;
        }

        // Online softmax (row reductions via shfl across the 16 tx lanes)
        #pragma unroll
        for (int i = 0; i < 4; i++) {
            float rm = fmaxf(fmaxf(acc[i][0], acc[i][1]), fmaxf(acc[i][2], acc[i][3]));
            rm = fmaxf(rm, __shfl_xor_sync(0xffffffffu, rm, 1));
            rm = fmaxf(rm, __shfl_xor_sync(0xffffffffu, rm, 2));
            rm = fmaxf(rm, __shfl_xor_sync(0xffffffffu, rm, 4));
            rm = fmaxf(rm, __shfl_xor_sync(0xffffffffu, rm, 8));
            float mnew = fmaxf(m_i[i], rm);
            float sc   = __expf(m_i[i] - mnew);     // exp(-inf)=0 on first tile
            float s = 0.f;
            #pragma unroll
            for (int jj = 0; jj < 4; jj++) {
                float p = __expf(acc[i][jj] - mnew);
                Ps[(ty * 4 + i) * 65 + tx * 4 + jj] = p;
                s += p;
            }
            s += __shfl_xor_sync(0xffffffffu, s, 1);
            s += __shfl_xor_sync(0xffffffffu, s, 2);
            s += __shfl_xor_sync(0xffffffffu, s, 4);
            s += __shfl_xor_sync(0xffffffffu, s, 8);
            l_i[i] = l_i[i] * sc + s;
            m_i[i] = mnew;
            #pragma unroll
            for (int jj = 0; jj < 8; jj++) O[i][jj] *= sc;
        }
        __syncthreads();  // Ps visible to all

        // O += P @ V (4 rows x 8 cols per thread)
        #pragma unroll 4
        for (int kk = 0; kk < FBN; kk++) {
            float vr[8];
            *(float4*)&vr[0] = *(float4*)&Vs[kk * HD + tx * 8];
            *(float4*)&vr[4] = *(float4*)&Vs[kk * HD + tx * 8 + 4];
            #pragma unroll
            for (int i = 0; i < 4; i++) {
                float p = Ps[(ty * 4 + i) * 65 + kk];
                #pragma unroll
                for (int jj = 0; jj < 8; jj++)
                    O[i][jj] = fmaf(p, vr[jj], O[i][jj]);
            }
        }
    }

    // Epilogue: normalize, write [B,T,C]
    #pragma unroll
    for (int i = 0; i < 4; i++) {
        float inv = 1.f / l_i[i];
        float o[8];
        #pragma unroll
        for (int jj = 0; jj < 8; jj++) o[jj] = O[i][jj] * inv;
        float* op = out + ((size_t)b * TSEQ + q0 + ty * 4 + i) * CDIM + h * HD + tx * 8;
        *(float4*)op       = *(float4*)&o[0];
        *(float4*)(op + 4) = *(float4*)&o[4];
    }
}

// ---------------------------------------------------------------------------
extern "C" void kernel_launch(void* const* d_in, const int* in_sizes, int n_in,
                              void* d_out, int out_size)
{
    const float* x      = (const float*)d_in[0];
    const float* w_attn = (const float*)d_in[1];
    const float* b_attn = (const float*)d_in[2];
    const float* w_proj = (const float*)d_in[3];
    const float* b_proj = (const float*)d_in[4];
    float* out = (float*)d_out;

    float *qkv, *att;
    cudaGetSymbolAddress((void**)&qkv, g_qkv);
    cudaGetSymbolAddress((void**)&att, g_att);

    cudaFuncSetAttribute(flash_kernel,
                         cudaFuncAttributeMaxDynamicSharedMemorySize, FLASH_SMEM);

    const int M = BDIM * TSEQ;  // 4096

    // 1) QKV = x @ w_attn + b_attn           [4096, 6144]
    sgemm_bias_kernel<<<dim3(3 * CDIM / 128, M / 128), 256>>>(
        x, w_attn, b_attn, qkv, M, 3 * CDIM, CDIM);

    // 2) Flash attention -> g_att            [4096, 2048]
    flash_kernel<<<dim3(TSEQ / FBM, NHEAD, BDIM), 256, FLASH_SMEM>>>(qkv, att);

    // 3) out = att @ w_proj + b_proj         [4096, 2048]
    sgemm_bias_kernel<<<dim3(CDIM / 128, M / 128), 256>>>(
        att, w_proj, b_proj, out, M, CDIM, CDIM);
}